// round 15
// baseline (speedup 1.0000x reference)
#include <cuda_runtime.h>
#include <cuda_fp16.h>
#include <cstdint>

// Problem constants
#define BATCH 2
#define SEQ   2048
#define DIM   1024
#define NH    16
#define HD    64
#define MROWS (BATCH * SEQ)   // 4096

#define FKT 64
#define FNT (SEQ / FKT)   // 32

// Scratch (allocation-free rule: __device__ globals)
__device__ __half g_Q[BATCH * NH * SEQ * HD];  // [b,h,s,hd] fp16, PRE-SCALED by CS
__device__ __half g_K[BATCH * NH * SEQ * HD];
__device__ __half g_V[BATCH * NH * SEQ * HD];
__device__ __half g_A[BATCH * SEQ * DIM];      // attn out [b,s,h*hd] fp16
__device__ __half g_Wh[4 * DIM * DIM];         // fp16 Wq,Wk,Wv,Wo
__device__ __half g_Xh[3 * (size_t)MROWS * DIM]; // fp16 q,k,v
__device__ float  g_bias_m[BATCH * SEQ];       // mask bias: -1e30 or 0
__device__ int    g_mflag[BATCH * FNT];        // per-(b, kv-tile) mask flag

#define CS 0.18033688f  // 0.125 * log2(e)

// ---------------------------------------------------------------------------
// Helpers
// ---------------------------------------------------------------------------
__device__ __forceinline__ uint32_t smem_u32(const void* p) {
    uint32_t a;
    asm("{ .reg .u64 t; cvta.to.shared.u64 t, %1; cvt.u32.u64 %0, t; }" : "=r"(a) : "l"(p));
    return a;
}

#define CP_ASYNC16(dst, src) \
    asm volatile("cp.async.cg.shared.global [%0], [%1], 16;" :: "r"(dst), "l"(src))
#define CP_ASYNC_COMMIT() asm volatile("cp.async.commit_group;" ::: "memory")
#define CP_ASYNC_WAIT(n)  asm volatile("cp.async.wait_group %0;" :: "n"(n) : "memory")

// fp16 MMA, fp32 accumulate: m16n8k16
#define MMA_F16(d, av, bv)                                                    \
    asm volatile("mma.sync.aligned.m16n8k16.row.col.f32.f16.f16.f32 "         \
                 "{%0,%1,%2,%3}, {%4,%5,%6,%7}, {%8,%9}, {%0,%1,%2,%3};"      \
                 : "+f"((d)[0]), "+f"((d)[1]), "+f"((d)[2]), "+f"((d)[3])     \
                 : "r"((av)[0]), "r"((av)[1]), "r"((av)[2]), "r"((av)[3]),    \
                   "r"((bv)[0]), "r"((bv)[1]))

#define LDSM_X4(r0, r1, r2, r3, addr)                                         \
    asm volatile("ldmatrix.sync.aligned.m8n8.x4.shared.b16 {%0,%1,%2,%3}, [%4];" \
                 : "=r"(r0), "=r"(r1), "=r"(r2), "=r"(r3) : "r"(addr))

#define LDSM_X4_T(r0, r1, r2, r3, addr)                                       \
    asm volatile("ldmatrix.sync.aligned.m8n8.x4.trans.shared.b16 {%0,%1,%2,%3}, [%4];" \
                 : "=r"(r0), "=r"(r1), "=r"(r2), "=r"(r3) : "r"(addr))

__device__ __forceinline__ uint32_t pack_h2(float a, float b) {
    __half2 h = __floats2half2_rn(a, b);
    return *(uint32_t*)&h;
}

// Fast exp2 on the FMA pipe, deg-4 poly. Rel err ~4e-5.
__device__ __forceinline__ float fast_exp2(float x) {
    x = fmaxf(x, -126.0f);
    float t = x + 12582912.0f;            // 2^23 + 2^22
    float i = t - 12582912.0f;
    float f = x - i;
    float p = 9.6181291e-3f;
    p = fmaf(p, f, 5.5504109e-2f);
    p = fmaf(p, f, 2.4022651e-1f);
    p = fmaf(p, f, 6.9314718e-1f);
    p = fmaf(p, f, 1.0f);
    int ib = __float_as_int(t) << 23;     // == i << 23 exactly
    return __int_as_float(__float_as_int(p) + ib);
}

// ---------------------------------------------------------------------------
// Fused fp32 -> fp16 conversion pre-pass (7 arrays + mask prep, one launch).
// ---------------------------------------------------------------------------
struct ConvArgs {
    const float* src[7];
    __half* dst[7];
    int n8[7];     // number of 8-float groups
    const int* mask;
    float* bias_m;
    int* mflag;
};

__global__ __launch_bounds__(256) void conv_f16_all(ConvArgs a) {
    const int seg = blockIdx.y;
    const int tid = threadIdx.x;
    if (seg == 7) {
        if (blockIdx.x != 0) return;
        for (int i = tid; i < BATCH * SEQ; i += 256) {
            a.bias_m[i] = a.mask[i] ? -1e30f : 0.f;
        }
        if (tid < BATCH * FNT) {
            int f = 0;
#pragma unroll 4
            for (int j = 0; j < FKT; j++) f |= a.mask[tid * FKT + j];
            a.mflag[tid] = f ? 1 : 0;
        }
        return;
    }
    const float* src = a.src[seg];
    __half* dst = a.dst[seg];
    const int n8 = a.n8[seg];
    int i0 = blockIdx.x * 1024 + tid;
    if (i0 >= n8) return;
#pragma unroll
    for (int t = 0; t < 4; t++) {
        int idx = i0 + t * 256;
        if (idx < n8) {
            float4 v0 = ((const float4*)src)[2 * idx];
            float4 v1 = ((const float4*)src)[2 * idx + 1];
            uint4 o;
            o.x = pack_h2(v0.x, v0.y);
            o.y = pack_h2(v0.z, v0.w);
            o.z = pack_h2(v1.x, v1.y);
            o.w = pack_h2(v1.z, v1.w);
            ((uint4*)dst)[idx] = o;
        }
    }
}

// ---------------------------------------------------------------------------
// fp16 mma.sync GEMM, 3-stage cp.async ring, one __syncthreads per k-tile.
// CTA tile 128x128, BK=64, 256 threads = 8 warps (4m x 2n), 32x64. 2 CTAs/SM.
// SPLIT_HEADS path multiplies output by scale (CS for Q, 1.0 for K/V).
// ---------------------------------------------------------------------------
#define GBM 128
#define GBN 128
#define GBK 64
#define NKT (DIM / GBK)                 // 16
#define SA_BYTES (GBM * GBK * 2)        // 16384
#define SB_BYTES (GBN * GBK * 2)        // 16384
#define NSTAGE 3
#define SM_GEMM_TOTAL (NSTAGE * (SA_BYTES + SB_BYTES))   // 98304

struct GemmArgs {
    const __half* A;
    const __half* W;
    const float* bias;
    void* C;
    float scale;
};

template <int SPLIT_HEADS>
__device__ __forceinline__ void gemm_body(const __half* __restrict__ A,
                                          const __half* __restrict__ W,
                                          const float* __restrict__ bias,
                                          void* __restrict__ Cv,
                                          float scale) {
    extern __shared__ char smem[];
    const uint32_t sA = smem_u32(smem);
    const uint32_t sB = sA + NSTAGE * SA_BYTES;

    const int tid = threadIdx.x;
    const int lane = tid & 31;
    const int wid = tid >> 5;      // 0..7
    const int wm = wid & 3;        // 0..3 (m: 4 x 32)
    const int wn = wid >> 2;       // 0..1 (n: 2 x 64)
    const int g = lane >> 2;
    const int tig = lane & 3;
    const int m0 = blockIdx.y * GBM;
    const int n0 = blockIdx.x * GBN;

    // ldmatrix lane decomposition
    const int jL = lane >> 3;
    const int iL = lane & 7;
    const int rA0 = wm * 32 + (jL & 1) * 8 + iL;
    const int rA1 = rA0 + 16;
    const int cA = jL >> 1;
    const int cB = jL & 1;
    int rB[4];
#pragma unroll
    for (int bg = 0; bg < 4; bg++) rB[bg] = wn * 64 + bg * 16 + (jL >> 1) * 8 + iL;

    float acc[2][8][4];
#pragma unroll
    for (int i = 0; i < 2; i++)
#pragma unroll
        for (int j = 0; j < 8; j++)
#pragma unroll
            for (int c = 0; c < 4; c++) acc[i][j][c] = 0.f;

    auto stage = [&](int kt, int buf) {
        const int k0 = kt * GBK;    // halves
#pragma unroll
        for (int t = 0; t < 4; t++) {
            int idx = tid + t * 256;
            int row = idx >> 3;
            int c = idx & 7;
            uint32_t dst = sA + buf * SA_BYTES + row * 128 + ((c ^ (row & 7)) << 4);
            CP_ASYNC16(dst, &A[(size_t)(m0 + row) * DIM + k0 + c * 8]);
        }
#pragma unroll
        for (int t = 0; t < 4; t++) {
            int idx = tid + t * 256;
            int row = idx >> 3;
            int c = idx & 7;
            uint32_t dst = sB + buf * SB_BYTES + row * 128 + ((c ^ (row & 7)) << 4);
            CP_ASYNC16(dst, &W[(size_t)(n0 + row) * DIM + k0 + c * 8]);
        }
    };

    stage(0, 0);
    CP_ASYNC_COMMIT();
    stage(1, 1);
    CP_ASYNC_COMMIT();

    int bi = 0, bs = 2;
    for (int kt = 0; kt < NKT; kt++) {
        if (kt < NKT - 1) {
            CP_ASYNC_WAIT(1);
        } else {
            CP_ASYNC_WAIT(0);
        }
        __syncthreads();
        if (kt + 2 < NKT) {
            stage(kt + 2, bs);
            CP_ASYNC_COMMIT();
        }

        const uint32_t abuf = sA + bi * SA_BYTES;
        const uint32_t bbuf = sB + bi * SB_BYTES;
#pragma unroll
        for (int s = 0; s < 4; s++) {
            uint32_t a[2][4];
            {
                int ch = 2 * s + cA;
                uint32_t ad0 = abuf + rA0 * 128 + ((ch ^ (rA0 & 7)) << 4);
                uint32_t ad1 = abuf + rA1 * 128 + ((ch ^ (rA1 & 7)) << 4);
                LDSM_X4(a[0][0], a[0][1], a[0][2], a[0][3], ad0);
                LDSM_X4(a[1][0], a[1][1], a[1][2], a[1][3], ad1);
            }
            uint32_t bf[8][2];
            {
                int ch = 2 * s + cB;
#pragma unroll
                for (int bg = 0; bg < 4; bg++) {
                    uint32_t ad = bbuf + rB[bg] * 128 + ((ch ^ (rB[bg] & 7)) << 4);
                    LDSM_X4(bf[2 * bg][0], bf[2 * bg][1],
                            bf[2 * bg + 1][0], bf[2 * bg + 1][1], ad);
                }
            }
#pragma unroll
            for (int i = 0; i < 2; i++)
#pragma unroll
                for (int j = 0; j < 8; j++) MMA_F16(acc[i][j], a[i], bf[j]);
        }
        bi = (bi == NSTAGE - 1) ? 0 : bi + 1;
        bs = (bs == NSTAGE - 1) ? 0 : bs + 1;
    }

#pragma unroll
    for (int i = 0; i < 2; i++) {
        const int m1 = m0 + wm * 32 + i * 16 + g;
        const int m2 = m1 + 8;
#pragma unroll
        for (int j = 0; j < 8; j++) {
            const int n = n0 + wn * 64 + j * 8 + tig * 2;
            const float2 bb = *(const float2*)&bias[n];
            if (SPLIT_HEADS) {
                __half* C = (__half*)Cv;
                uint32_t h1 = pack_h2((acc[i][j][0] + bb.x) * scale,
                                      (acc[i][j][1] + bb.y) * scale);
                uint32_t h2 = pack_h2((acc[i][j][2] + bb.x) * scale,
                                      (acc[i][j][3] + bb.y) * scale);
                int h = n >> 6;
                int hd = n & (HD - 1);
                {
                    int b = m1 >> 11, sq = m1 & (SEQ - 1);
                    *(uint32_t*)&C[((size_t)((b * NH + h) * SEQ + sq)) * HD + hd] = h1;
                }
                {
                    int b = m2 >> 11, sq = m2 & (SEQ - 1);
                    *(uint32_t*)&C[((size_t)((b * NH + h) * SEQ + sq)) * HD + hd] = h2;
                }
            } else {
                float* C = (float*)Cv;
                float2 r1, r2;
                r1.x = acc[i][j][0] + bb.x;
                r1.y = acc[i][j][1] + bb.y;
                r2.x = acc[i][j][2] + bb.x;
                r2.y = acc[i][j][3] + bb.y;
                *(float2*)&C[(size_t)m1 * DIM + n] = r1;
                *(float2*)&C[(size_t)m2 * DIM + n] = r2;
            }
        }
    }
}

__global__ __launch_bounds__(256, 2) void gemm_qkv(GemmArgs a0, GemmArgs a1, GemmArgs a2) {
    const GemmArgs& a = (blockIdx.z == 0) ? a0 : (blockIdx.z == 1) ? a1 : a2;
    gemm_body<1>(a.A, a.W, a.bias, a.C, a.scale);
}

__global__ __launch_bounds__(256, 2) void gemm_out(const __half* __restrict__ A,
                                                   const __half* __restrict__ W,
                                                   const float* __restrict__ bias,
                                                   float* __restrict__ C) {
    gemm_body<0>(A, W, bias, C, 1.0f);
}

// ---------------------------------------------------------------------------
// fp16 flash attention: 256 threads (8 warps) = 256 q-rows/CTA -> grid 256
// CTAs = ONE wave. Q pre-scaled (S in log2-domain), register-passed P,
// ldmatrix K/V, 3-stage KV ring, per-thread partial l, mask via uniform flag.
// ---------------------------------------------------------------------------
#define KVROW 144         // bytes per KV row (64 halves + 8 pad)
#define KBUF (FKT * KVROW)        // 9216
#define B_K 0
#define B_V (3 * KBUF)            // 27648
#define FLASH_SMEM_BYTES (6 * KBUF)  // 55296

__global__ __launch_bounds__(256, 1) void flash_attn_tc(__half* __restrict__ Out) {
    extern __shared__ char smem[];
    const uint32_t sbase = smem_u32(smem);

    const int b = blockIdx.z;
    const int h = blockIdx.y;
    const int tid = threadIdx.x;
    const int w = tid >> 5;        // 0..7
    const int lane = tid & 31;
    const int g = lane >> 2;
    const int tig = lane & 3;
    const int jL = lane >> 3;
    const int iL = lane & 7;
    const int qr0 = blockIdx.x * 256 + w * 32;

    const __half* Qp = g_Q + ((size_t)((b * NH + h) * SEQ) + qr0) * HD;
    const __half* Kb = g_K + ((size_t)((b * NH + h) * SEQ)) * HD;
    const __half* Vb = g_V + ((size_t)((b * NH + h) * SEQ)) * HD;

    // Persistent Q A-fragments (pre-scaled by CS)
    uint32_t aQ[2][4][4];
#pragma unroll
    for (int mi = 0; mi < 2; mi++) {
        const __half* Qm = Qp + (size_t)(16 * mi) * HD;
#pragma unroll
        for (int s = 0; s < 4; s++) {
            aQ[mi][s][0] = *(const uint32_t*)&Qm[g * HD + s * 16 + tig * 2];
            aQ[mi][s][1] = *(const uint32_t*)&Qm[(g + 8) * HD + s * 16 + tig * 2];
            aQ[mi][s][2] = *(const uint32_t*)&Qm[g * HD + s * 16 + 8 + tig * 2];
            aQ[mi][s][3] = *(const uint32_t*)&Qm[(g + 8) * HD + s * 16 + 8 + tig * 2];
        }
    }

    float oacc[2][8][4];
#pragma unroll
    for (int mi = 0; mi < 2; mi++)
#pragma unroll
        for (int j = 0; j < 8; j++)
#pragma unroll
            for (int c = 0; c < 4; c++) oacc[mi][j][c] = 0.f;
    float mrun[4] = {-1e30f, -1e30f, -1e30f, -1e30f};
    float lrun[4] = {0.f, 0.f, 0.f, 0.f};   // per-thread PARTIAL sums

    auto stage = [&](int kt, int buf) {
        const __half* Kg = Kb + (size_t)kt * FKT * HD;
        const __half* Vg = Vb + (size_t)kt * FKT * HD;
        const uint32_t dK = sbase + B_K + buf * KBUF;
        const uint32_t dV = sbase + B_V + buf * KBUF;
#pragma unroll
        for (int t = 0; t < 2; t++) {
            int idx = tid + t * 256;       // 0..511
            int row = idx >> 3;            // 0..63
            int c = idx & 7;               // 16B chunk
            CP_ASYNC16(dK + row * KVROW + c * 16, &Kg[row * HD + c * 8]);
            CP_ASYNC16(dV + row * KVROW + c * 16, &Vg[row * HD + c * 8]);
        }
    };

    stage(0, 0);
    CP_ASYNC_COMMIT();
    stage(1, 1);
    CP_ASYNC_COMMIT();

    const int knrow_base = (jL >> 1) * 8 + iL;
    const int kcol = (jL & 1) * 16;
    const int vkrow_base = (jL & 1) * 8 + iL;
    const int vcol = (jL >> 1) * 16;

    int bi = 0, bs = 2;
    for (int kt = 0; kt < FNT; kt++) {
        if (kt < FNT - 1) {
            CP_ASYNC_WAIT(1);
        } else {
            CP_ASYNC_WAIT(0);
        }
        __syncthreads();
        if (kt + 2 < FNT) {
            stage(kt + 2, bs);
            CP_ASYNC_COMMIT();
        }

        const uint32_t Kbuf = sbase + B_K + bi * KBUF;
        const uint32_t Vbuf = sbase + B_V + bi * KBUF;

        // ---- S = Q @ K^T (32 x 64 per warp), 4 k16-steps ----
        float sc[2][8][4];
#pragma unroll
        for (int mi = 0; mi < 2; mi++)
#pragma unroll
            for (int j = 0; j < 8; j++)
#pragma unroll
                for (int c = 0; c < 4; c++) sc[mi][j][c] = 0.f;
#pragma unroll
        for (int s = 0; s < 4; s++) {
            uint32_t bf[8][2];
#pragma unroll
            for (int kg = 0; kg < 4; kg++) {
                uint32_t ad = Kbuf + (16 * kg + knrow_base) * KVROW + s * 32 + kcol;
                LDSM_X4(bf[2 * kg][0], bf[2 * kg][1],
                        bf[2 * kg + 1][0], bf[2 * kg + 1][1], ad);
            }
#pragma unroll
            for (int jn = 0; jn < 8; jn++) {
                MMA_F16(sc[0][jn], aQ[0][s], bf[jn]);
                MMA_F16(sc[1][jn], aQ[1][s], bf[jn]);
            }
        }

        // ---- rare mask path (uniform branch; mask typically all-zero) ----
        if (g_mflag[b * FNT + kt]) {
            const float* bm = g_bias_m + b * SEQ + kt * FKT;
#pragma unroll
            for (int jn = 0; jn < 8; jn++) {
                float2 bv2 = *(const float2*)&bm[8 * jn + 2 * tig];
#pragma unroll
                for (int mi = 0; mi < 2; mi++) {
                    sc[mi][jn][0] += bv2.x;
                    sc[mi][jn][1] += bv2.y;
                    sc[mi][jn][2] += bv2.x;
                    sc[mi][jn][3] += bv2.y;
                }
            }
        }

        // ---- online softmax (S already in log2 domain) ----
#pragma unroll
        for (int mi = 0; mi < 2; mi++) {
            float mx0 = -1e30f, mx1 = -1e30f;
#pragma unroll
            for (int jn = 0; jn < 8; jn++) {
                mx0 = fmaxf(mx0, fmaxf(sc[mi][jn][0], sc[mi][jn][1]));
                mx1 = fmaxf(mx1, fmaxf(sc[mi][jn][2], sc[mi][jn][3]));
            }
            mx0 = fmaxf(mx0, __shfl_xor_sync(0xFFFFFFFF, mx0, 1));
            mx0 = fmaxf(mx0, __shfl_xor_sync(0xFFFFFFFF, mx0, 2));
            mx1 = fmaxf(mx1, __shfl_xor_sync(0xFFFFFFFF, mx1, 1));
            mx1 = fmaxf(mx1, __shfl_xor_sync(0xFFFFFFFF, mx1, 2));

            const float nm0 = fmaxf(mrun[2 * mi], mx0);
            const float nm1 = fmaxf(mrun[2 * mi + 1], mx1);
            const float cor0 = fast_exp2(mrun[2 * mi] - nm0);
            const float cor1 = fast_exp2(mrun[2 * mi + 1] - nm1);
            mrun[2 * mi] = nm0;
            mrun[2 * mi + 1] = nm1;

            float s0 = 0.f, s1 = 0.f;
#pragma unroll
            for (int jn = 0; jn < 8; jn++) {
                sc[mi][jn][0] = fast_exp2(sc[mi][jn][0] - nm0);
                sc[mi][jn][1] = fast_exp2(sc[mi][jn][1] - nm0);
                sc[mi][jn][2] = fast_exp2(sc[mi][jn][2] - nm1);
                sc[mi][jn][3] = fast_exp2(sc[mi][jn][3] - nm1);
                s0 += sc[mi][jn][0] + sc[mi][jn][1];
                s1 += sc[mi][jn][2] + sc[mi][jn][3];
            }
            lrun[2 * mi] = lrun[2 * mi] * cor0 + s0;
            lrun[2 * mi + 1] = lrun[2 * mi + 1] * cor1 + s1;

#pragma unroll
            for (int j = 0; j < 8; j++) {
                oacc[mi][j][0] *= cor0;
                oacc[mi][j][1] *= cor0;
                oacc[mi][j][2] *= cor1;
                oacc[mi][j][3] *= cor1;
            }
        }

        // ---- O += P @ V: P from sc registers, V via ldmatrix.trans ----
#pragma unroll
        for (int s2 = 0; s2 < 4; s2++) {
            uint32_t pa0[4], pa1[4];
            pa0[0] = pack_h2(sc[0][2 * s2][0],     sc[0][2 * s2][1]);
            pa0[1] = pack_h2(sc[0][2 * s2][2],     sc[0][2 * s2][3]);
            pa0[2] = pack_h2(sc[0][2 * s2 + 1][0], sc[0][2 * s2 + 1][1]);
            pa0[3] = pack_h2(sc[0][2 * s2 + 1][2], sc[0][2 * s2 + 1][3]);
            pa1[0] = pack_h2(sc[1][2 * s2][0],     sc[1][2 * s2][1]);
            pa1[1] = pack_h2(sc[1][2 * s2][2],     sc[1][2 * s2][3]);
            pa1[2] = pack_h2(sc[1][2 * s2 + 1][0], sc[1][2 * s2 + 1][1]);
            pa1[3] = pack_h2(sc[1][2 * s2 + 1][2], sc[1][2 * s2 + 1][3]);

            uint32_t bv[8][2];
#pragma unroll
            for (int vg = 0; vg < 4; vg++) {
                uint32_t ad = Vbuf + (16 * s2 + vkrow_base) * KVROW + vg * 32 + vcol;
                LDSM_X4_T(bv[2 * vg][0], bv[2 * vg][1],
                          bv[2 * vg + 1][0], bv[2 * vg + 1][1], ad);
            }
#pragma unroll
            for (int jn2 = 0; jn2 < 8; jn2++) {
                MMA_F16(oacc[0][jn2], pa0, bv[jn2]);
                MMA_F16(oacc[1][jn2], pa1, bv[jn2]);
            }
        }
        bi = (bi == 2) ? 0 : bi + 1;
        bs = (bs == 2) ? 0 : bs + 1;
    }

    // ---- quad-reduce partial l once, then normalize + store ----
#pragma unroll
    for (int i = 0; i < 4; i++) {
        lrun[i] += __shfl_xor_sync(0xFFFFFFFF, lrun[i], 1);
        lrun[i] += __shfl_xor_sync(0xFFFFFFFF, lrun[i], 2);
    }
#pragma unroll
    for (int mi = 0; mi < 2; mi++) {
        const float il0 = 1.f / lrun[2 * mi];
        const float il1 = 1.f / lrun[2 * mi + 1];
        __half* O0 = Out + ((size_t)(b * SEQ + qr0 + 16 * mi + g)) * DIM + h * HD;
        __half* O1 = Out + ((size_t)(b * SEQ + qr0 + 16 * mi + g + 8)) * DIM + h * HD;
#pragma unroll
        for (int jn2 = 0; jn2 < 8; jn2++) {
            *(uint32_t*)&O0[8 * jn2 + 2 * tig] =
                pack_h2(oacc[mi][jn2][0] * il0, oacc[mi][jn2][1] * il0);
            *(uint32_t*)&O1[8 * jn2 + 2 * tig] =
                pack_h2(oacc[mi][jn2][2] * il1, oacc[mi][jn2][3] * il1);
        }
    }
}

// ---------------------------------------------------------------------------
extern "C" void kernel_launch(void* const* d_in, const int* in_sizes, int n_in,
                              void* d_out, int out_size) {
    const float* q  = (const float*)d_in[0];
    const float* k  = (const float*)d_in[1];
    const float* v  = (const float*)d_in[2];
    const int* mask = (const int*)d_in[3];
    const float* Wq = (const float*)d_in[4];
    const float* bq = (const float*)d_in[5];
    const float* Wk = (const float*)d_in[6];
    const float* bk = (const float*)d_in[7];
    const float* Wv = (const float*)d_in[8];
    const float* bv = (const float*)d_in[9];
    const float* Wo = (const float*)d_in[10];
    const float* bo = (const float*)d_in[11];
    float* out = (float*)d_out;

    __half *pQ, *pK, *pV, *pA, *pWh, *pXh;
    float* pBm;
    int* pMf;
    cudaGetSymbolAddress((void**)&pQ, g_Q);
    cudaGetSymbolAddress((void**)&pK, g_K);
    cudaGetSymbolAddress((void**)&pV, g_V);
    cudaGetSymbolAddress((void**)&pA, g_A);
    cudaGetSymbolAddress((void**)&pWh, g_Wh);
    cudaGetSymbolAddress((void**)&pXh, g_Xh);
    cudaGetSymbolAddress((void**)&pBm, g_bias_m);
    cudaGetSymbolAddress((void**)&pMf, g_mflag);

    cudaFuncSetAttribute(gemm_qkv, cudaFuncAttributeMaxDynamicSharedMemorySize, SM_GEMM_TOTAL);
    cudaFuncSetAttribute(gemm_out, cudaFuncAttributeMaxDynamicSharedMemorySize, SM_GEMM_TOTAL);
    cudaFuncSetAttribute(flash_attn_tc, cudaFuncAttributeMaxDynamicSharedMemorySize, FLASH_SMEM_BYTES);

    // --- fused fp32 -> fp16 pre-pass + mask prep ---
    const int W8 = DIM * DIM / 8;       // 131072
    const int X8 = MROWS * DIM / 8;     // 524288
    ConvArgs ca;
    ca.src[0] = Wq; ca.dst[0] = pWh + 0 * (size_t)DIM * DIM; ca.n8[0] = W8;
    ca.src[1] = Wk; ca.dst[1] = pWh + 1 * (size_t)DIM * DIM; ca.n8[1] = W8;
    ca.src[2] = Wv; ca.dst[2] = pWh + 2 * (size_t)DIM * DIM; ca.n8[2] = W8;
    ca.src[3] = Wo; ca.dst[3] = pWh + 3 * (size_t)DIM * DIM; ca.n8[3] = W8;
    ca.src[4] = q;  ca.dst[4] = pXh + 0 * (size_t)MROWS * DIM; ca.n8[4] = X8;
    ca.src[5] = k;  ca.dst[5] = pXh + 1 * (size_t)MROWS * DIM; ca.n8[5] = X8;
    ca.src[6] = v;  ca.dst[6] = pXh + 2 * (size_t)MROWS * DIM; ca.n8[6] = X8;
    ca.mask = mask;
    ca.bias_m = pBm;
    ca.mflag = pMf;
    conv_f16_all<<<dim3(X8 / 1024, 8), 256>>>(ca);

    GemmArgs aq{pXh + 0 * (size_t)MROWS * DIM, pWh + 0 * (size_t)DIM * DIM, bq, pQ, CS};
    GemmArgs ak{pXh + 1 * (size_t)MROWS * DIM, pWh + 1 * (size_t)DIM * DIM, bk, pK, 1.0f};
    GemmArgs av{pXh + 2 * (size_t)MROWS * DIM, pWh + 2 * (size_t)DIM * DIM, bv, pV, 1.0f};

    dim3 gqkv(DIM / GBN, MROWS / GBM, 3);   // (8, 32, 3) = 768 CTAs
    gemm_qkv<<<gqkv, 256, SM_GEMM_TOTAL>>>(aq, ak, av);

    flash_attn_tc<<<dim3(SEQ / 256, NH, BATCH), 256, FLASH_SMEM_BYTES>>>(pA);

    dim3 go(DIM / GBN, MROWS / GBM);        // (8, 32) = 256 CTAs
    gemm_out<<<go, 256, SM_GEMM_TOTAL>>>(pA, pWh + 3 * (size_t)DIM * DIM, bo, out);
}

// round 16
// speedup vs baseline: 1.0154x; 1.0154x over previous
#include <cuda_runtime.h>
#include <cuda_fp16.h>
#include <cstdint>

// Problem constants
#define BATCH 2
#define SEQ   2048
#define DIM   1024
#define NH    16
#define HD    64
#define MROWS (BATCH * SEQ)   // 4096

#define FKT 64
#define FNT (SEQ / FKT)   // 32

// Scratch (allocation-free rule: __device__ globals)
__device__ __half g_Q[BATCH * NH * SEQ * HD];  // [b,h,s,hd] fp16, PRE-SCALED by CS
__device__ __half g_K[BATCH * NH * SEQ * HD];
__device__ __half g_V[BATCH * NH * SEQ * HD];
__device__ __half g_A[BATCH * SEQ * DIM];      // attn out [b,s,h*hd] fp16
__device__ __half g_Wh[4 * DIM * DIM];         // fp16 Wq,Wk,Wv,Wo
__device__ __half g_Xh[3 * (size_t)MROWS * DIM]; // fp16 q,k,v
__device__ float  g_bias_m[BATCH * SEQ];       // mask bias: -1e30 or 0
__device__ uint32_t g_mword[BATCH];            // bit kt set if tile kt has any mask

#define CS 0.18033688f  // 0.125 * log2(e)

// ---------------------------------------------------------------------------
// Helpers
// ---------------------------------------------------------------------------
__device__ __forceinline__ uint32_t smem_u32(const void* p) {
    uint32_t a;
    asm("{ .reg .u64 t; cvta.to.shared.u64 t, %1; cvt.u32.u64 %0, t; }" : "=r"(a) : "l"(p));
    return a;
}

#define CP_ASYNC16(dst, src) \
    asm volatile("cp.async.cg.shared.global [%0], [%1], 16;" :: "r"(dst), "l"(src))
#define CP_ASYNC_COMMIT() asm volatile("cp.async.commit_group;" ::: "memory")
#define CP_ASYNC_WAIT(n)  asm volatile("cp.async.wait_group %0;" :: "n"(n) : "memory")

// fp16 MMA, fp32 accumulate: m16n8k16
#define MMA_F16(d, av, bv)                                                    \
    asm volatile("mma.sync.aligned.m16n8k16.row.col.f32.f16.f16.f32 "         \
                 "{%0,%1,%2,%3}, {%4,%5,%6,%7}, {%8,%9}, {%0,%1,%2,%3};"      \
                 : "+f"((d)[0]), "+f"((d)[1]), "+f"((d)[2]), "+f"((d)[3])     \
                 : "r"((av)[0]), "r"((av)[1]), "r"((av)[2]), "r"((av)[3]),    \
                   "r"((bv)[0]), "r"((bv)[1]))

#define LDSM_X4(r0, r1, r2, r3, addr)                                         \
    asm volatile("ldmatrix.sync.aligned.m8n8.x4.shared.b16 {%0,%1,%2,%3}, [%4];" \
                 : "=r"(r0), "=r"(r1), "=r"(r2), "=r"(r3) : "r"(addr))

#define LDSM_X4_T(r0, r1, r2, r3, addr)                                       \
    asm volatile("ldmatrix.sync.aligned.m8n8.x4.trans.shared.b16 {%0,%1,%2,%3}, [%4];" \
                 : "=r"(r0), "=r"(r1), "=r"(r2), "=r"(r3) : "r"(addr))

__device__ __forceinline__ uint32_t pack_h2(float a, float b) {
    __half2 h = __floats2half2_rn(a, b);
    return *(uint32_t*)&h;
}

// Fast exp2 on the FMA pipe, deg-4 poly. Rel err ~4e-5.
__device__ __forceinline__ float fast_exp2(float x) {
    x = fmaxf(x, -126.0f);
    float t = x + 12582912.0f;            // 2^23 + 2^22
    float i = t - 12582912.0f;
    float f = x - i;
    float p = 9.6181291e-3f;
    p = fmaf(p, f, 5.5504109e-2f);
    p = fmaf(p, f, 2.4022651e-1f);
    p = fmaf(p, f, 6.9314718e-1f);
    p = fmaf(p, f, 1.0f);
    int ib = __float_as_int(t) << 23;     // == i << 23 exactly
    return __int_as_float(__float_as_int(p) + ib);
}

// ---------------------------------------------------------------------------
// Fused fp32 -> fp16 conversion pre-pass (7 arrays + mask prep, one launch).
// ---------------------------------------------------------------------------
struct ConvArgs {
    const float* src[7];
    __half* dst[7];
    int n8[7];     // number of 8-float groups
    const int* mask;
    float* bias_m;
    uint32_t* mword;
};

__global__ __launch_bounds__(256) void conv_f16_all(ConvArgs a) {
    const int seg = blockIdx.y;
    const int tid = threadIdx.x;
    if (seg == 7) {
        if (blockIdx.x != 0) return;
        for (int i = tid; i < BATCH * SEQ; i += 256) {
            a.bias_m[i] = a.mask[i] ? -1e30f : 0.f;
        }
        if (tid < 64) {   // warps 0,1 fully active: tid 0..31 -> b=0, 32..63 -> b=1
            int f = 0;
#pragma unroll 4
            for (int j = 0; j < FKT; j++) f |= a.mask[tid * FKT + j];
            unsigned bal = __ballot_sync(0xFFFFFFFF, f != 0);
            if ((tid & 31) == 0) a.mword[tid >> 5] = bal;
        }
        return;
    }
    const float* src = a.src[seg];
    __half* dst = a.dst[seg];
    const int n8 = a.n8[seg];
    int i0 = blockIdx.x * 1024 + tid;
    if (i0 >= n8) return;
#pragma unroll
    for (int t = 0; t < 4; t++) {
        int idx = i0 + t * 256;
        if (idx < n8) {
            float4 v0 = ((const float4*)src)[2 * idx];
            float4 v1 = ((const float4*)src)[2 * idx + 1];
            uint4 o;
            o.x = pack_h2(v0.x, v0.y);
            o.y = pack_h2(v0.z, v0.w);
            o.z = pack_h2(v1.x, v1.y);
            o.w = pack_h2(v1.z, v1.w);
            ((uint4*)dst)[idx] = o;
        }
    }
}

// ---------------------------------------------------------------------------
// fp16 mma.sync GEMM, 3-stage cp.async ring, one __syncthreads per k-tile.
// CTA tile 128x128, BK=64, 256 threads = 8 warps (4m x 2n), 32x64. 2 CTAs/SM.
// SPLIT_HEADS path multiplies output by scale (CS for Q, 1.0 for K/V).
// ---------------------------------------------------------------------------
#define GBM 128
#define GBN 128
#define GBK 64
#define NKT (DIM / GBK)                 // 16
#define SA_BYTES (GBM * GBK * 2)        // 16384
#define SB_BYTES (GBN * GBK * 2)        // 16384
#define NSTAGE 3
#define SM_GEMM_TOTAL (NSTAGE * (SA_BYTES + SB_BYTES))   // 98304

struct GemmArgs {
    const __half* A;
    const __half* W;
    const float* bias;
    void* C;
    float scale;
};

template <int SPLIT_HEADS>
__device__ __forceinline__ void gemm_body(const __half* __restrict__ A,
                                          const __half* __restrict__ W,
                                          const float* __restrict__ bias,
                                          void* __restrict__ Cv,
                                          float scale) {
    extern __shared__ char smem[];
    const uint32_t sA = smem_u32(smem);
    const uint32_t sB = sA + NSTAGE * SA_BYTES;

    const int tid = threadIdx.x;
    const int lane = tid & 31;
    const int wid = tid >> 5;      // 0..7
    const int wm = wid & 3;        // 0..3 (m: 4 x 32)
    const int wn = wid >> 2;       // 0..1 (n: 2 x 64)
    const int g = lane >> 2;
    const int tig = lane & 3;
    const int m0 = blockIdx.y * GBM;
    const int n0 = blockIdx.x * GBN;

    // ldmatrix lane decomposition
    const int jL = lane >> 3;
    const int iL = lane & 7;
    const int rA0 = wm * 32 + (jL & 1) * 8 + iL;
    const int rA1 = rA0 + 16;
    const int cA = jL >> 1;
    const int cB = jL & 1;
    int rB[4];
#pragma unroll
    for (int bg = 0; bg < 4; bg++) rB[bg] = wn * 64 + bg * 16 + (jL >> 1) * 8 + iL;

    float acc[2][8][4];
#pragma unroll
    for (int i = 0; i < 2; i++)
#pragma unroll
        for (int j = 0; j < 8; j++)
#pragma unroll
            for (int c = 0; c < 4; c++) acc[i][j][c] = 0.f;

    auto stage = [&](int kt, int buf) {
        const int k0 = kt * GBK;    // halves
#pragma unroll
        for (int t = 0; t < 4; t++) {
            int idx = tid + t * 256;
            int row = idx >> 3;
            int c = idx & 7;
            uint32_t dst = sA + buf * SA_BYTES + row * 128 + ((c ^ (row & 7)) << 4);
            CP_ASYNC16(dst, &A[(size_t)(m0 + row) * DIM + k0 + c * 8]);
        }
#pragma unroll
        for (int t = 0; t < 4; t++) {
            int idx = tid + t * 256;
            int row = idx >> 3;
            int c = idx & 7;
            uint32_t dst = sB + buf * SB_BYTES + row * 128 + ((c ^ (row & 7)) << 4);
            CP_ASYNC16(dst, &W[(size_t)(n0 + row) * DIM + k0 + c * 8]);
        }
    };

    stage(0, 0);
    CP_ASYNC_COMMIT();
    stage(1, 1);
    CP_ASYNC_COMMIT();

    int bi = 0, bs = 2;
    for (int kt = 0; kt < NKT; kt++) {
        if (kt < NKT - 1) {
            CP_ASYNC_WAIT(1);
        } else {
            CP_ASYNC_WAIT(0);
        }
        __syncthreads();
        if (kt + 2 < NKT) {
            stage(kt + 2, bs);
            CP_ASYNC_COMMIT();
        }

        const uint32_t abuf = sA + bi * SA_BYTES;
        const uint32_t bbuf = sB + bi * SB_BYTES;
#pragma unroll
        for (int s = 0; s < 4; s++) {
            uint32_t a[2][4];
            {
                int ch = 2 * s + cA;
                uint32_t ad0 = abuf + rA0 * 128 + ((ch ^ (rA0 & 7)) << 4);
                uint32_t ad1 = abuf + rA1 * 128 + ((ch ^ (rA1 & 7)) << 4);
                LDSM_X4(a[0][0], a[0][1], a[0][2], a[0][3], ad0);
                LDSM_X4(a[1][0], a[1][1], a[1][2], a[1][3], ad1);
            }
            uint32_t bf[8][2];
            {
                int ch = 2 * s + cB;
#pragma unroll
                for (int bg = 0; bg < 4; bg++) {
                    uint32_t ad = bbuf + rB[bg] * 128 + ((ch ^ (rB[bg] & 7)) << 4);
                    LDSM_X4(bf[2 * bg][0], bf[2 * bg][1],
                            bf[2 * bg + 1][0], bf[2 * bg + 1][1], ad);
                }
            }
#pragma unroll
            for (int i = 0; i < 2; i++)
#pragma unroll
                for (int j = 0; j < 8; j++) MMA_F16(acc[i][j], a[i], bf[j]);
        }
        bi = (bi == NSTAGE - 1) ? 0 : bi + 1;
        bs = (bs == NSTAGE - 1) ? 0 : bs + 1;
    }

#pragma unroll
    for (int i = 0; i < 2; i++) {
        const int m1 = m0 + wm * 32 + i * 16 + g;
        const int m2 = m1 + 8;
#pragma unroll
        for (int j = 0; j < 8; j++) {
            const int n = n0 + wn * 64 + j * 8 + tig * 2;
            const float2 bb = *(const float2*)&bias[n];
            if (SPLIT_HEADS) {
                __half* C = (__half*)Cv;
                uint32_t h1 = pack_h2((acc[i][j][0] + bb.x) * scale,
                                      (acc[i][j][1] + bb.y) * scale);
                uint32_t h2 = pack_h2((acc[i][j][2] + bb.x) * scale,
                                      (acc[i][j][3] + bb.y) * scale);
                int h = n >> 6;
                int hd = n & (HD - 1);
                {
                    int b = m1 >> 11, sq = m1 & (SEQ - 1);
                    *(uint32_t*)&C[((size_t)((b * NH + h) * SEQ + sq)) * HD + hd] = h1;
                }
                {
                    int b = m2 >> 11, sq = m2 & (SEQ - 1);
                    *(uint32_t*)&C[((size_t)((b * NH + h) * SEQ + sq)) * HD + hd] = h2;
                }
            } else {
                float* C = (float*)Cv;
                float2 r1, r2;
                r1.x = acc[i][j][0] + bb.x;
                r1.y = acc[i][j][1] + bb.y;
                r2.x = acc[i][j][2] + bb.x;
                r2.y = acc[i][j][3] + bb.y;
                *(float2*)&C[(size_t)m1 * DIM + n] = r1;
                *(float2*)&C[(size_t)m2 * DIM + n] = r2;
            }
        }
    }
}

__global__ __launch_bounds__(256, 2) void gemm_qkv(GemmArgs a0, GemmArgs a1, GemmArgs a2) {
    const GemmArgs& a = (blockIdx.z == 0) ? a0 : (blockIdx.z == 1) ? a1 : a2;
    gemm_body<1>(a.A, a.W, a.bias, a.C, a.scale);
}

__global__ __launch_bounds__(256, 2) void gemm_out(const __half* __restrict__ A,
                                                   const __half* __restrict__ W,
                                                   const float* __restrict__ bias,
                                                   float* __restrict__ C) {
    gemm_body<0>(A, W, bias, C, 1.0f);
}

// ---------------------------------------------------------------------------
// fp16 flash attention (R14 config, proven): 128 thr (4 warps), 128 q-rows/CTA,
// 2 CTAs/SM. Q pre-scaled (S in log2-domain), register-passed P, ldmatrix K/V,
// 3-stage KV ring, per-thread partial l, mask via per-batch BITMASK word.
// ---------------------------------------------------------------------------
#define KVROW 144         // bytes per KV row (64 halves + 8 pad)
#define KBUF (FKT * KVROW)        // 9216
#define B_K 0
#define B_V (3 * KBUF)            // 27648
#define FLASH_SMEM_BYTES (6 * KBUF)  // 55296

__global__ __launch_bounds__(128) void flash_attn_tc(__half* __restrict__ Out) {
    extern __shared__ char smem[];
    const uint32_t sbase = smem_u32(smem);

    const int b = blockIdx.z;
    const int h = blockIdx.y;
    const int tid = threadIdx.x;
    const int w = tid >> 5;
    const int lane = tid & 31;
    const int g = lane >> 2;
    const int tig = lane & 3;
    const int jL = lane >> 3;
    const int iL = lane & 7;
    const int qr0 = blockIdx.x * 128 + w * 32;

    const __half* Qp = g_Q + ((size_t)((b * NH + h) * SEQ) + qr0) * HD;
    const __half* Kb = g_K + ((size_t)((b * NH + h) * SEQ)) * HD;
    const __half* Vb = g_V + ((size_t)((b * NH + h) * SEQ)) * HD;
    const uint32_t mbits = g_mword[b];    // one load, replaces 32 in-loop loads

    // Persistent Q A-fragments (pre-scaled by CS)
    uint32_t aQ[2][4][4];
#pragma unroll
    for (int mi = 0; mi < 2; mi++) {
        const __half* Qm = Qp + (size_t)(16 * mi) * HD;
#pragma unroll
        for (int s = 0; s < 4; s++) {
            aQ[mi][s][0] = *(const uint32_t*)&Qm[g * HD + s * 16 + tig * 2];
            aQ[mi][s][1] = *(const uint32_t*)&Qm[(g + 8) * HD + s * 16 + tig * 2];
            aQ[mi][s][2] = *(const uint32_t*)&Qm[g * HD + s * 16 + 8 + tig * 2];
            aQ[mi][s][3] = *(const uint32_t*)&Qm[(g + 8) * HD + s * 16 + 8 + tig * 2];
        }
    }

    float oacc[2][8][4];
#pragma unroll
    for (int mi = 0; mi < 2; mi++)
#pragma unroll
        for (int j = 0; j < 8; j++)
#pragma unroll
            for (int c = 0; c < 4; c++) oacc[mi][j][c] = 0.f;
    float mrun[4] = {-1e30f, -1e30f, -1e30f, -1e30f};
    float lrun[4] = {0.f, 0.f, 0.f, 0.f};   // per-thread PARTIAL sums

    auto stage = [&](int kt, int buf) {
        const __half* Kg = Kb + (size_t)kt * FKT * HD;
        const __half* Vg = Vb + (size_t)kt * FKT * HD;
        const uint32_t dK = sbase + B_K + buf * KBUF;
        const uint32_t dV = sbase + B_V + buf * KBUF;
#pragma unroll
        for (int t = 0; t < 4; t++) {
            int idx = tid + t * 128;       // 0..511
            int row = idx >> 3;            // 0..63
            int c = idx & 7;               // 16B chunk
            CP_ASYNC16(dK + row * KVROW + c * 16, &Kg[row * HD + c * 8]);
            CP_ASYNC16(dV + row * KVROW + c * 16, &Vg[row * HD + c * 8]);
        }
    };

    stage(0, 0);
    CP_ASYNC_COMMIT();
    stage(1, 1);
    CP_ASYNC_COMMIT();

    const int knrow_base = (jL >> 1) * 8 + iL;
    const int kcol = (jL & 1) * 16;
    const int vkrow_base = (jL & 1) * 8 + iL;
    const int vcol = (jL >> 1) * 16;

    int bi = 0, bs = 2;
    for (int kt = 0; kt < FNT; kt++) {
        if (kt < FNT - 1) {
            CP_ASYNC_WAIT(1);
        } else {
            CP_ASYNC_WAIT(0);
        }
        __syncthreads();
        if (kt + 2 < FNT) {
            stage(kt + 2, bs);
            CP_ASYNC_COMMIT();
        }

        const uint32_t Kbuf = sbase + B_K + bi * KBUF;
        const uint32_t Vbuf = sbase + B_V + bi * KBUF;

        // ---- S = Q @ K^T (32 x 64 per warp), 4 k16-steps ----
        float sc[2][8][4];
#pragma unroll
        for (int mi = 0; mi < 2; mi++)
#pragma unroll
            for (int j = 0; j < 8; j++)
#pragma unroll
                for (int c = 0; c < 4; c++) sc[mi][j][c] = 0.f;
#pragma unroll
        for (int s = 0; s < 4; s++) {
            uint32_t bf[8][2];
#pragma unroll
            for (int kg = 0; kg < 4; kg++) {
                uint32_t ad = Kbuf + (16 * kg + knrow_base) * KVROW + s * 32 + kcol;
                LDSM_X4(bf[2 * kg][0], bf[2 * kg][1],
                        bf[2 * kg + 1][0], bf[2 * kg + 1][1], ad);
            }
#pragma unroll
            for (int jn = 0; jn < 8; jn++) {
                MMA_F16(sc[0][jn], aQ[0][s], bf[jn]);
                MMA_F16(sc[1][jn], aQ[1][s], bf[jn]);
            }
        }

        // ---- rare mask path (register bit test; mask typically all-zero) ----
        if (mbits & (1u << kt)) {
            const float* bm = g_bias_m + b * SEQ + kt * FKT;
#pragma unroll
            for (int jn = 0; jn < 8; jn++) {
                float2 bv2 = *(const float2*)&bm[8 * jn + 2 * tig];
#pragma unroll
                for (int mi = 0; mi < 2; mi++) {
                    sc[mi][jn][0] += bv2.x;
                    sc[mi][jn][1] += bv2.y;
                    sc[mi][jn][2] += bv2.x;
                    sc[mi][jn][3] += bv2.y;
                }
            }
        }

        // ---- online softmax (S already in log2 domain) ----
#pragma unroll
        for (int mi = 0; mi < 2; mi++) {
            float mx0 = -1e30f, mx1 = -1e30f;
#pragma unroll
            for (int jn = 0; jn < 8; jn++) {
                mx0 = fmaxf(mx0, fmaxf(sc[mi][jn][0], sc[mi][jn][1]));
                mx1 = fmaxf(mx1, fmaxf(sc[mi][jn][2], sc[mi][jn][3]));
            }
            mx0 = fmaxf(mx0, __shfl_xor_sync(0xFFFFFFFF, mx0, 1));
            mx0 = fmaxf(mx0, __shfl_xor_sync(0xFFFFFFFF, mx0, 2));
            mx1 = fmaxf(mx1, __shfl_xor_sync(0xFFFFFFFF, mx1, 1));
            mx1 = fmaxf(mx1, __shfl_xor_sync(0xFFFFFFFF, mx1, 2));

            const float nm0 = fmaxf(mrun[2 * mi], mx0);
            const float nm1 = fmaxf(mrun[2 * mi + 1], mx1);
            const float cor0 = fast_exp2(mrun[2 * mi] - nm0);
            const float cor1 = fast_exp2(mrun[2 * mi + 1] - nm1);
            mrun[2 * mi] = nm0;
            mrun[2 * mi + 1] = nm1;

            float s0 = 0.f, s1 = 0.f;
#pragma unroll
            for (int jn = 0; jn < 8; jn++) {
                sc[mi][jn][0] = fast_exp2(sc[mi][jn][0] - nm0);
                sc[mi][jn][1] = fast_exp2(sc[mi][jn][1] - nm0);
                sc[mi][jn][2] = fast_exp2(sc[mi][jn][2] - nm1);
                sc[mi][jn][3] = fast_exp2(sc[mi][jn][3] - nm1);
                s0 += sc[mi][jn][0] + sc[mi][jn][1];
                s1 += sc[mi][jn][2] + sc[mi][jn][3];
            }
            lrun[2 * mi] = lrun[2 * mi] * cor0 + s0;
            lrun[2 * mi + 1] = lrun[2 * mi + 1] * cor1 + s1;

#pragma unroll
            for (int j = 0; j < 8; j++) {
                oacc[mi][j][0] *= cor0;
                oacc[mi][j][1] *= cor0;
                oacc[mi][j][2] *= cor1;
                oacc[mi][j][3] *= cor1;
            }
        }

        // ---- O += P @ V: P from sc registers, V via ldmatrix.trans ----
#pragma unroll
        for (int s2 = 0; s2 < 4; s2++) {
            uint32_t pa0[4], pa1[4];
            pa0[0] = pack_h2(sc[0][2 * s2][0],     sc[0][2 * s2][1]);
            pa0[1] = pack_h2(sc[0][2 * s2][2],     sc[0][2 * s2][3]);
            pa0[2] = pack_h2(sc[0][2 * s2 + 1][0], sc[0][2 * s2 + 1][1]);
            pa0[3] = pack_h2(sc[0][2 * s2 + 1][2], sc[0][2 * s2 + 1][3]);
            pa1[0] = pack_h2(sc[1][2 * s2][0],     sc[1][2 * s2][1]);
            pa1[1] = pack_h2(sc[1][2 * s2][2],     sc[1][2 * s2][3]);
            pa1[2] = pack_h2(sc[1][2 * s2 + 1][0], sc[1][2 * s2 + 1][1]);
            pa1[3] = pack_h2(sc[1][2 * s2 + 1][2], sc[1][2 * s2 + 1][3]);

            uint32_t bv[8][2];
#pragma unroll
            for (int vg = 0; vg < 4; vg++) {
                uint32_t ad = Vbuf + (16 * s2 + vkrow_base) * KVROW + vg * 32 + vcol;
                LDSM_X4_T(bv[2 * vg][0], bv[2 * vg][1],
                          bv[2 * vg + 1][0], bv[2 * vg + 1][1], ad);
            }
#pragma unroll
            for (int jn2 = 0; jn2 < 8; jn2++) {
                MMA_F16(oacc[0][jn2], pa0, bv[jn2]);
                MMA_F16(oacc[1][jn2], pa1, bv[jn2]);
            }
        }
        bi = (bi == 2) ? 0 : bi + 1;
        bs = (bs == 2) ? 0 : bs + 1;
    }

    // ---- quad-reduce partial l once, then normalize + store ----
#pragma unroll
    for (int i = 0; i < 4; i++) {
        lrun[i] += __shfl_xor_sync(0xFFFFFFFF, lrun[i], 1);
        lrun[i] += __shfl_xor_sync(0xFFFFFFFF, lrun[i], 2);
    }
#pragma unroll
    for (int mi = 0; mi < 2; mi++) {
        const float il0 = 1.f / lrun[2 * mi];
        const float il1 = 1.f / lrun[2 * mi + 1];
        __half* O0 = Out + ((size_t)(b * SEQ + qr0 + 16 * mi + g)) * DIM + h * HD;
        __half* O1 = Out + ((size_t)(b * SEQ + qr0 + 16 * mi + g + 8)) * DIM + h * HD;
#pragma unroll
        for (int jn2 = 0; jn2 < 8; jn2++) {
            *(uint32_t*)&O0[8 * jn2 + 2 * tig] =
                pack_h2(oacc[mi][jn2][0] * il0, oacc[mi][jn2][1] * il0);
            *(uint32_t*)&O1[8 * jn2 + 2 * tig] =
                pack_h2(oacc[mi][jn2][2] * il1, oacc[mi][jn2][3] * il1);
        }
    }
}

// ---------------------------------------------------------------------------
extern "C" void kernel_launch(void* const* d_in, const int* in_sizes, int n_in,
                              void* d_out, int out_size) {
    const float* q  = (const float*)d_in[0];
    const float* k  = (const float*)d_in[1];
    const float* v  = (const float*)d_in[2];
    const int* mask = (const int*)d_in[3];
    const float* Wq = (const float*)d_in[4];
    const float* bq = (const float*)d_in[5];
    const float* Wk = (const float*)d_in[6];
    const float* bk = (const float*)d_in[7];
    const float* Wv = (const float*)d_in[8];
    const float* bv = (const float*)d_in[9];
    const float* Wo = (const float*)d_in[10];
    const float* bo = (const float*)d_in[11];
    float* out = (float*)d_out;

    __half *pQ, *pK, *pV, *pA, *pWh, *pXh;
    float* pBm;
    uint32_t* pMw;
    cudaGetSymbolAddress((void**)&pQ, g_Q);
    cudaGetSymbolAddress((void**)&pK, g_K);
    cudaGetSymbolAddress((void**)&pV, g_V);
    cudaGetSymbolAddress((void**)&pA, g_A);
    cudaGetSymbolAddress((void**)&pWh, g_Wh);
    cudaGetSymbolAddress((void**)&pXh, g_Xh);
    cudaGetSymbolAddress((void**)&pBm, g_bias_m);
    cudaGetSymbolAddress((void**)&pMw, g_mword);

    cudaFuncSetAttribute(gemm_qkv, cudaFuncAttributeMaxDynamicSharedMemorySize, SM_GEMM_TOTAL);
    cudaFuncSetAttribute(gemm_out, cudaFuncAttributeMaxDynamicSharedMemorySize, SM_GEMM_TOTAL);
    cudaFuncSetAttribute(flash_attn_tc, cudaFuncAttributeMaxDynamicSharedMemorySize, FLASH_SMEM_BYTES);

    // --- fused fp32 -> fp16 pre-pass + mask prep ---
    const int W8 = DIM * DIM / 8;       // 131072
    const int X8 = MROWS * DIM / 8;     // 524288
    ConvArgs ca;
    ca.src[0] = Wq; ca.dst[0] = pWh + 0 * (size_t)DIM * DIM; ca.n8[0] = W8;
    ca.src[1] = Wk; ca.dst[1] = pWh + 1 * (size_t)DIM * DIM; ca.n8[1] = W8;
    ca.src[2] = Wv; ca.dst[2] = pWh + 2 * (size_t)DIM * DIM; ca.n8[2] = W8;
    ca.src[3] = Wo; ca.dst[3] = pWh + 3 * (size_t)DIM * DIM; ca.n8[3] = W8;
    ca.src[4] = q;  ca.dst[4] = pXh + 0 * (size_t)MROWS * DIM; ca.n8[4] = X8;
    ca.src[5] = k;  ca.dst[5] = pXh + 1 * (size_t)MROWS * DIM; ca.n8[5] = X8;
    ca.src[6] = v;  ca.dst[6] = pXh + 2 * (size_t)MROWS * DIM; ca.n8[6] = X8;
    ca.mask = mask;
    ca.bias_m = pBm;
    ca.mword = pMw;
    conv_f16_all<<<dim3(X8 / 1024, 8), 256>>>(ca);

    GemmArgs aq{pXh + 0 * (size_t)MROWS * DIM, pWh + 0 * (size_t)DIM * DIM, bq, pQ, CS};
    GemmArgs ak{pXh + 1 * (size_t)MROWS * DIM, pWh + 1 * (size_t)DIM * DIM, bk, pK, 1.0f};
    GemmArgs av{pXh + 2 * (size_t)MROWS * DIM, pWh + 2 * (size_t)DIM * DIM, bv, pV, 1.0f};

    dim3 gqkv(DIM / GBN, MROWS / GBM, 3);   // (8, 32, 3) = 768 CTAs
    gemm_qkv<<<gqkv, 256, SM_GEMM_TOTAL>>>(aq, ak, av);

    flash_attn_tc<<<dim3(SEQ / 128, NH, BATCH), 128, FLASH_SMEM_BYTES>>>(pA);

    dim3 go(DIM / GBN, MROWS / GBM);        // (8, 32) = 256 CTAs
    gemm_out<<<go, 256, SM_GEMM_TOTAL>>>(pA, pWh + 3 * (size_t)DIM * DIM, bo, out);
}

// round 17
// speedup vs baseline: 1.0332x; 1.0176x over previous
#include <cuda_runtime.h>
#include <cuda_fp16.h>
#include <cstdint>

// Problem constants
#define BATCH 2
#define SEQ   2048
#define DIM   1024
#define NH    16
#define HD    64
#define MROWS (BATCH * SEQ)   // 4096

#define FKT 64
#define FNT (SEQ / FKT)   // 32

// Scratch (allocation-free rule: __device__ globals)
__device__ __half g_Q[BATCH * NH * SEQ * HD];  // [b,h,s,hd] fp16, PRE-SCALED by CS
__device__ __half g_K[BATCH * NH * SEQ * HD];
__device__ __half g_V[BATCH * NH * SEQ * HD];
__device__ __half g_A[BATCH * SEQ * DIM];      // attn out [b,s,h*hd] fp16
__device__ __half g_Wh[4 * DIM * DIM];         // fp16 Wq,Wk,Wv,Wo
__device__ __half g_Xh[3 * (size_t)MROWS * DIM]; // fp16 q,k,v
__device__ float  g_bias_m[BATCH * SEQ];       // mask bias: -1e30 or 0
__device__ uint32_t g_mword[BATCH];            // bit kt set if tile kt has any mask

#define CS 0.18033688f  // 0.125 * log2(e)

// ---------------------------------------------------------------------------
// Helpers
// ---------------------------------------------------------------------------
__device__ __forceinline__ uint32_t smem_u32(const void* p) {
    uint32_t a;
    asm("{ .reg .u64 t; cvta.to.shared.u64 t, %1; cvt.u32.u64 %0, t; }" : "=r"(a) : "l"(p));
    return a;
}

#define CP_ASYNC16(dst, src) \
    asm volatile("cp.async.cg.shared.global [%0], [%1], 16;" :: "r"(dst), "l"(src))
#define CP_ASYNC_COMMIT() asm volatile("cp.async.commit_group;" ::: "memory")
#define CP_ASYNC_WAIT(n)  asm volatile("cp.async.wait_group %0;" :: "n"(n) : "memory")

// fp16 MMA, fp32 accumulate: m16n8k16
#define MMA_F16(d, av, bv)                                                    \
    asm volatile("mma.sync.aligned.m16n8k16.row.col.f32.f16.f16.f32 "         \
                 "{%0,%1,%2,%3}, {%4,%5,%6,%7}, {%8,%9}, {%0,%1,%2,%3};"      \
                 : "+f"((d)[0]), "+f"((d)[1]), "+f"((d)[2]), "+f"((d)[3])     \
                 : "r"((av)[0]), "r"((av)[1]), "r"((av)[2]), "r"((av)[3]),    \
                   "r"((bv)[0]), "r"((bv)[1]))

#define LDSM_X4(r0, r1, r2, r3, addr)                                         \
    asm volatile("ldmatrix.sync.aligned.m8n8.x4.shared.b16 {%0,%1,%2,%3}, [%4];" \
                 : "=r"(r0), "=r"(r1), "=r"(r2), "=r"(r3) : "r"(addr))

#define LDSM_X4_T(r0, r1, r2, r3, addr)                                       \
    asm volatile("ldmatrix.sync.aligned.m8n8.x4.trans.shared.b16 {%0,%1,%2,%3}, [%4];" \
                 : "=r"(r0), "=r"(r1), "=r"(r2), "=r"(r3) : "r"(addr))

__device__ __forceinline__ uint32_t pack_h2(float a, float b) {
    __half2 h = __floats2half2_rn(a, b);
    return *(uint32_t*)&h;
}

// Fast exp2 on the FMA pipe, deg-4 poly. Rel err ~4e-5.
__device__ __forceinline__ float fast_exp2(float x) {
    x = fmaxf(x, -126.0f);
    float t = x + 12582912.0f;            // 2^23 + 2^22
    float i = t - 12582912.0f;
    float f = x - i;
    float p = 9.6181291e-3f;
    p = fmaf(p, f, 5.5504109e-2f);
    p = fmaf(p, f, 2.4022651e-1f);
    p = fmaf(p, f, 6.9314718e-1f);
    p = fmaf(p, f, 1.0f);
    int ib = __float_as_int(t) << 23;     // == i << 23 exactly
    return __int_as_float(__float_as_int(p) + ib);
}

// ---------------------------------------------------------------------------
// Fused fp32 -> fp16 conversion pre-pass (7 arrays + mask prep, one launch).
// Mask segment spread across all blockIdx.x (no single-block straggler).
// ---------------------------------------------------------------------------
struct ConvArgs {
    const float* src[7];
    __half* dst[7];
    int n8[7];     // number of 8-float groups
    const int* mask;
    float* bias_m;
    uint32_t* mword;
};

__global__ __launch_bounds__(256) void conv_f16_all(ConvArgs a) {
    const int seg = blockIdx.y;
    const int tid = threadIdx.x;
    if (seg == 7) {
        // bias floats: spread BATCH*SEQ = 4096 elems over 16 blocks x 256 thr
        int gi = blockIdx.x * 256 + tid;
        if (gi < BATCH * SEQ) {
            a.bias_m[gi] = a.mask[gi] ? -1e30f : 0.f;
        }
        // per-tile flags: block 0, warps 0-1 (tid 0..31 -> b=0, 32..63 -> b=1)
        if (blockIdx.x == 0 && tid < 64) {
            int f = 0;
#pragma unroll 4
            for (int j = 0; j < FKT; j++) f |= a.mask[tid * FKT + j];
            unsigned bal = __ballot_sync(0xFFFFFFFF, f != 0);
            if ((tid & 31) == 0) a.mword[tid >> 5] = bal;
        }
        return;
    }
    const float* src = a.src[seg];
    __half* dst = a.dst[seg];
    const int n8 = a.n8[seg];
    int i0 = blockIdx.x * 1024 + tid;
    if (i0 >= n8) return;
#pragma unroll
    for (int t = 0; t < 4; t++) {
        int idx = i0 + t * 256;
        if (idx < n8) {
            float4 v0 = ((const float4*)src)[2 * idx];
            float4 v1 = ((const float4*)src)[2 * idx + 1];
            uint4 o;
            o.x = pack_h2(v0.x, v0.y);
            o.y = pack_h2(v0.z, v0.w);
            o.z = pack_h2(v1.x, v1.y);
            o.w = pack_h2(v1.z, v1.w);
            ((uint4*)dst)[idx] = o;
        }
    }
}

// ---------------------------------------------------------------------------
// fp16 mma.sync GEMM, 3-stage cp.async ring, one __syncthreads per k-tile.
// CTA tile 128x128, BK=64, 256 threads = 8 warps (4m x 2n), 32x64. 2 CTAs/SM.
// SPLIT_HEADS path multiplies output by scale (CS for Q, 1.0 for K/V).
// ---------------------------------------------------------------------------
#define GBM 128
#define GBN 128
#define GBK 64
#define NKT (DIM / GBK)                 // 16
#define SA_BYTES (GBM * GBK * 2)        // 16384
#define SB_BYTES (GBN * GBK * 2)        // 16384
#define NSTAGE 3
#define SM_GEMM_TOTAL (NSTAGE * (SA_BYTES + SB_BYTES))   // 98304

struct GemmArgs {
    const __half* A;
    const __half* W;
    const float* bias;
    void* C;
    float scale;
};

template <int SPLIT_HEADS>
__device__ __forceinline__ void gemm_body(const __half* __restrict__ A,
                                          const __half* __restrict__ W,
                                          const float* __restrict__ bias,
                                          void* __restrict__ Cv,
                                          float scale) {
    extern __shared__ char smem[];
    const uint32_t sA = smem_u32(smem);
    const uint32_t sB = sA + NSTAGE * SA_BYTES;

    const int tid = threadIdx.x;
    const int lane = tid & 31;
    const int wid = tid >> 5;      // 0..7
    const int wm = wid & 3;        // 0..3 (m: 4 x 32)
    const int wn = wid >> 2;       // 0..1 (n: 2 x 64)
    const int g = lane >> 2;
    const int tig = lane & 3;
    const int m0 = blockIdx.y * GBM;
    const int n0 = blockIdx.x * GBN;

    // ldmatrix lane decomposition
    const int jL = lane >> 3;
    const int iL = lane & 7;
    const int rA0 = wm * 32 + (jL & 1) * 8 + iL;
    const int rA1 = rA0 + 16;
    const int cA = jL >> 1;
    const int cB = jL & 1;
    int rB[4];
#pragma unroll
    for (int bg = 0; bg < 4; bg++) rB[bg] = wn * 64 + bg * 16 + (jL >> 1) * 8 + iL;

    float acc[2][8][4];
#pragma unroll
    for (int i = 0; i < 2; i++)
#pragma unroll
        for (int j = 0; j < 8; j++)
#pragma unroll
            for (int c = 0; c < 4; c++) acc[i][j][c] = 0.f;

    auto stage = [&](int kt, int buf) {
        const int k0 = kt * GBK;    // halves
#pragma unroll
        for (int t = 0; t < 4; t++) {
            int idx = tid + t * 256;
            int row = idx >> 3;
            int c = idx & 7;
            uint32_t dst = sA + buf * SA_BYTES + row * 128 + ((c ^ (row & 7)) << 4);
            CP_ASYNC16(dst, &A[(size_t)(m0 + row) * DIM + k0 + c * 8]);
        }
#pragma unroll
        for (int t = 0; t < 4; t++) {
            int idx = tid + t * 256;
            int row = idx >> 3;
            int c = idx & 7;
            uint32_t dst = sB + buf * SB_BYTES + row * 128 + ((c ^ (row & 7)) << 4);
            CP_ASYNC16(dst, &W[(size_t)(n0 + row) * DIM + k0 + c * 8]);
        }
    };

    stage(0, 0);
    CP_ASYNC_COMMIT();
    stage(1, 1);
    CP_ASYNC_COMMIT();

    int bi = 0, bs = 2;
    for (int kt = 0; kt < NKT; kt++) {
        if (kt < NKT - 1) {
            CP_ASYNC_WAIT(1);
        } else {
            CP_ASYNC_WAIT(0);
        }
        __syncthreads();
        if (kt + 2 < NKT) {
            stage(kt + 2, bs);
            CP_ASYNC_COMMIT();
        }

        const uint32_t abuf = sA + bi * SA_BYTES;
        const uint32_t bbuf = sB + bi * SB_BYTES;
#pragma unroll
        for (int s = 0; s < 4; s++) {
            uint32_t a[2][4];
            {
                int ch = 2 * s + cA;
                uint32_t ad0 = abuf + rA0 * 128 + ((ch ^ (rA0 & 7)) << 4);
                uint32_t ad1 = abuf + rA1 * 128 + ((ch ^ (rA1 & 7)) << 4);
                LDSM_X4(a[0][0], a[0][1], a[0][2], a[0][3], ad0);
                LDSM_X4(a[1][0], a[1][1], a[1][2], a[1][3], ad1);
            }
            uint32_t bf[8][2];
            {
                int ch = 2 * s + cB;
#pragma unroll
                for (int bg = 0; bg < 4; bg++) {
                    uint32_t ad = bbuf + rB[bg] * 128 + ((ch ^ (rB[bg] & 7)) << 4);
                    LDSM_X4(bf[2 * bg][0], bf[2 * bg][1],
                            bf[2 * bg + 1][0], bf[2 * bg + 1][1], ad);
                }
            }
#pragma unroll
            for (int i = 0; i < 2; i++)
#pragma unroll
                for (int j = 0; j < 8; j++) MMA_F16(acc[i][j], a[i], bf[j]);
        }
        bi = (bi == NSTAGE - 1) ? 0 : bi + 1;
        bs = (bs == NSTAGE - 1) ? 0 : bs + 1;
    }

#pragma unroll
    for (int i = 0; i < 2; i++) {
        const int m1 = m0 + wm * 32 + i * 16 + g;
        const int m2 = m1 + 8;
#pragma unroll
        for (int j = 0; j < 8; j++) {
            const int n = n0 + wn * 64 + j * 8 + tig * 2;
            const float2 bb = *(const float2*)&bias[n];
            if (SPLIT_HEADS) {
                __half* C = (__half*)Cv;
                uint32_t h1 = pack_h2((acc[i][j][0] + bb.x) * scale,
                                      (acc[i][j][1] + bb.y) * scale);
                uint32_t h2 = pack_h2((acc[i][j][2] + bb.x) * scale,
                                      (acc[i][j][3] + bb.y) * scale);
                int h = n >> 6;
                int hd = n & (HD - 1);
                {
                    int b = m1 >> 11, sq = m1 & (SEQ - 1);
                    *(uint32_t*)&C[((size_t)((b * NH + h) * SEQ + sq)) * HD + hd] = h1;
                }
                {
                    int b = m2 >> 11, sq = m2 & (SEQ - 1);
                    *(uint32_t*)&C[((size_t)((b * NH + h) * SEQ + sq)) * HD + hd] = h2;
                }
            } else {
                float* C = (float*)Cv;
                float2 r1, r2;
                r1.x = acc[i][j][0] + bb.x;
                r1.y = acc[i][j][1] + bb.y;
                r2.x = acc[i][j][2] + bb.x;
                r2.y = acc[i][j][3] + bb.y;
                *(float2*)&C[(size_t)m1 * DIM + n] = r1;
                *(float2*)&C[(size_t)m2 * DIM + n] = r2;
            }
        }
    }
}

__global__ __launch_bounds__(256, 2) void gemm_qkv(GemmArgs a0, GemmArgs a1, GemmArgs a2) {
    const GemmArgs& a = (blockIdx.z == 0) ? a0 : (blockIdx.z == 1) ? a1 : a2;
    gemm_body<1>(a.A, a.W, a.bias, a.C, a.scale);
}

__global__ __launch_bounds__(256, 2) void gemm_out(const __half* __restrict__ A,
                                                   const __half* __restrict__ W,
                                                   const float* __restrict__ bias,
                                                   float* __restrict__ C) {
    gemm_body<0>(A, W, bias, C, 1.0f);
}

// ---------------------------------------------------------------------------
// fp16 flash attention (proven config): 128 thr (4 warps), 128 q-rows/CTA,
// 2 CTAs/SM. Q pre-scaled (S in log2-domain), register-passed P, ldmatrix K/V,
// 3-stage KV ring, per-thread partial l, mask via per-batch BITMASK word.
// ---------------------------------------------------------------------------
#define KVROW 144         // bytes per KV row (64 halves + 8 pad)
#define KBUF (FKT * KVROW)        // 9216
#define B_K 0
#define B_V (3 * KBUF)            // 27648
#define FLASH_SMEM_BYTES (6 * KBUF)  // 55296

__global__ __launch_bounds__(128) void flash_attn_tc(__half* __restrict__ Out) {
    extern __shared__ char smem[];
    const uint32_t sbase = smem_u32(smem);

    const int b = blockIdx.z;
    const int h = blockIdx.y;
    const int tid = threadIdx.x;
    const int w = tid >> 5;
    const int lane = tid & 31;
    const int g = lane >> 2;
    const int tig = lane & 3;
    const int jL = lane >> 3;
    const int iL = lane & 7;
    const int qr0 = blockIdx.x * 128 + w * 32;

    const __half* Qp = g_Q + ((size_t)((b * NH + h) * SEQ) + qr0) * HD;
    const __half* Kb = g_K + ((size_t)((b * NH + h) * SEQ)) * HD;
    const __half* Vb = g_V + ((size_t)((b * NH + h) * SEQ)) * HD;
    const uint32_t mbits = g_mword[b];    // one load, replaces in-loop loads

    // Persistent Q A-fragments (pre-scaled by CS)
    uint32_t aQ[2][4][4];
#pragma unroll
    for (int mi = 0; mi < 2; mi++) {
        const __half* Qm = Qp + (size_t)(16 * mi) * HD;
#pragma unroll
        for (int s = 0; s < 4; s++) {
            aQ[mi][s][0] = *(const uint32_t*)&Qm[g * HD + s * 16 + tig * 2];
            aQ[mi][s][1] = *(const uint32_t*)&Qm[(g + 8) * HD + s * 16 + tig * 2];
            aQ[mi][s][2] = *(const uint32_t*)&Qm[g * HD + s * 16 + 8 + tig * 2];
            aQ[mi][s][3] = *(const uint32_t*)&Qm[(g + 8) * HD + s * 16 + 8 + tig * 2];
        }
    }

    float oacc[2][8][4];
#pragma unroll
    for (int mi = 0; mi < 2; mi++)
#pragma unroll
        for (int j = 0; j < 8; j++)
#pragma unroll
            for (int c = 0; c < 4; c++) oacc[mi][j][c] = 0.f;
    float mrun[4] = {-1e30f, -1e30f, -1e30f, -1e30f};
    float lrun[4] = {0.f, 0.f, 0.f, 0.f};   // per-thread PARTIAL sums

    auto stage = [&](int kt, int buf) {
        const __half* Kg = Kb + (size_t)kt * FKT * HD;
        const __half* Vg = Vb + (size_t)kt * FKT * HD;
        const uint32_t dK = sbase + B_K + buf * KBUF;
        const uint32_t dV = sbase + B_V + buf * KBUF;
#pragma unroll
        for (int t = 0; t < 4; t++) {
            int idx = tid + t * 128;       // 0..511
            int row = idx >> 3;            // 0..63
            int c = idx & 7;               // 16B chunk
            CP_ASYNC16(dK + row * KVROW + c * 16, &Kg[row * HD + c * 8]);
            CP_ASYNC16(dV + row * KVROW + c * 16, &Vg[row * HD + c * 8]);
        }
    };

    stage(0, 0);
    CP_ASYNC_COMMIT();
    stage(1, 1);
    CP_ASYNC_COMMIT();

    const int knrow_base = (jL >> 1) * 8 + iL;
    const int kcol = (jL & 1) * 16;
    const int vkrow_base = (jL & 1) * 8 + iL;
    const int vcol = (jL >> 1) * 16;

    int bi = 0, bs = 2;
    for (int kt = 0; kt < FNT; kt++) {
        if (kt < FNT - 1) {
            CP_ASYNC_WAIT(1);
        } else {
            CP_ASYNC_WAIT(0);
        }
        __syncthreads();
        if (kt + 2 < FNT) {
            stage(kt + 2, bs);
            CP_ASYNC_COMMIT();
        }

        const uint32_t Kbuf = sbase + B_K + bi * KBUF;
        const uint32_t Vbuf = sbase + B_V + bi * KBUF;

        // ---- S = Q @ K^T (32 x 64 per warp), 4 k16-steps ----
        float sc[2][8][4];
#pragma unroll
        for (int mi = 0; mi < 2; mi++)
#pragma unroll
            for (int j = 0; j < 8; j++)
#pragma unroll
                for (int c = 0; c < 4; c++) sc[mi][j][c] = 0.f;
#pragma unroll
        for (int s = 0; s < 4; s++) {
            uint32_t bf[8][2];
#pragma unroll
            for (int kg = 0; kg < 4; kg++) {
                uint32_t ad = Kbuf + (16 * kg + knrow_base) * KVROW + s * 32 + kcol;
                LDSM_X4(bf[2 * kg][0], bf[2 * kg][1],
                        bf[2 * kg + 1][0], bf[2 * kg + 1][1], ad);
            }
#pragma unroll
            for (int jn = 0; jn < 8; jn++) {
                MMA_F16(sc[0][jn], aQ[0][s], bf[jn]);
                MMA_F16(sc[1][jn], aQ[1][s], bf[jn]);
            }
        }

        // ---- rare mask path (register bit test; mask typically all-zero) ----
        if (mbits & (1u << kt)) {
            const float* bm = g_bias_m + b * SEQ + kt * FKT;
#pragma unroll
            for (int jn = 0; jn < 8; jn++) {
                float2 bv2 = *(const float2*)&bm[8 * jn + 2 * tig];
#pragma unroll
                for (int mi = 0; mi < 2; mi++) {
                    sc[mi][jn][0] += bv2.x;
                    sc[mi][jn][1] += bv2.y;
                    sc[mi][jn][2] += bv2.x;
                    sc[mi][jn][3] += bv2.y;
                }
            }
        }

        // ---- online softmax (S already in log2 domain) ----
#pragma unroll
        for (int mi = 0; mi < 2; mi++) {
            float mx0 = -1e30f, mx1 = -1e30f;
#pragma unroll
            for (int jn = 0; jn < 8; jn++) {
                mx0 = fmaxf(mx0, fmaxf(sc[mi][jn][0], sc[mi][jn][1]));
                mx1 = fmaxf(mx1, fmaxf(sc[mi][jn][2], sc[mi][jn][3]));
            }
            mx0 = fmaxf(mx0, __shfl_xor_sync(0xFFFFFFFF, mx0, 1));
            mx0 = fmaxf(mx0, __shfl_xor_sync(0xFFFFFFFF, mx0, 2));
            mx1 = fmaxf(mx1, __shfl_xor_sync(0xFFFFFFFF, mx1, 1));
            mx1 = fmaxf(mx1, __shfl_xor_sync(0xFFFFFFFF, mx1, 2));

            const float nm0 = fmaxf(mrun[2 * mi], mx0);
            const float nm1 = fmaxf(mrun[2 * mi + 1], mx1);
            const float cor0 = fast_exp2(mrun[2 * mi] - nm0);
            const float cor1 = fast_exp2(mrun[2 * mi + 1] - nm1);
            mrun[2 * mi] = nm0;
            mrun[2 * mi + 1] = nm1;

            float s0 = 0.f, s1 = 0.f;
#pragma unroll
            for (int jn = 0; jn < 8; jn++) {
                sc[mi][jn][0] = fast_exp2(sc[mi][jn][0] - nm0);
                sc[mi][jn][1] = fast_exp2(sc[mi][jn][1] - nm0);
                sc[mi][jn][2] = fast_exp2(sc[mi][jn][2] - nm1);
                sc[mi][jn][3] = fast_exp2(sc[mi][jn][3] - nm1);
                s0 += sc[mi][jn][0] + sc[mi][jn][1];
                s1 += sc[mi][jn][2] + sc[mi][jn][3];
            }
            lrun[2 * mi] = lrun[2 * mi] * cor0 + s0;
            lrun[2 * mi + 1] = lrun[2 * mi + 1] * cor1 + s1;

#pragma unroll
            for (int j = 0; j < 8; j++) {
                oacc[mi][j][0] *= cor0;
                oacc[mi][j][1] *= cor0;
                oacc[mi][j][2] *= cor1;
                oacc[mi][j][3] *= cor1;
            }
        }

        // ---- O += P @ V: P from sc registers, V via ldmatrix.trans ----
#pragma unroll
        for (int s2 = 0; s2 < 4; s2++) {
            uint32_t pa0[4], pa1[4];
            pa0[0] = pack_h2(sc[0][2 * s2][0],     sc[0][2 * s2][1]);
            pa0[1] = pack_h2(sc[0][2 * s2][2],     sc[0][2 * s2][3]);
            pa0[2] = pack_h2(sc[0][2 * s2 + 1][0], sc[0][2 * s2 + 1][1]);
            pa0[3] = pack_h2(sc[0][2 * s2 + 1][2], sc[0][2 * s2 + 1][3]);
            pa1[0] = pack_h2(sc[1][2 * s2][0],     sc[1][2 * s2][1]);
            pa1[1] = pack_h2(sc[1][2 * s2][2],     sc[1][2 * s2][3]);
            pa1[2] = pack_h2(sc[1][2 * s2 + 1][0], sc[1][2 * s2 + 1][1]);
            pa1[3] = pack_h2(sc[1][2 * s2 + 1][2], sc[1][2 * s2 + 1][3]);

            uint32_t bv[8][2];
#pragma unroll
            for (int vg = 0; vg < 4; vg++) {
                uint32_t ad = Vbuf + (16 * s2 + vkrow_base) * KVROW + vg * 32 + vcol;
                LDSM_X4_T(bv[2 * vg][0], bv[2 * vg][1],
                          bv[2 * vg + 1][0], bv[2 * vg + 1][1], ad);
            }
#pragma unroll
            for (int jn2 = 0; jn2 < 8; jn2++) {
                MMA_F16(oacc[0][jn2], pa0, bv[jn2]);
                MMA_F16(oacc[1][jn2], pa1, bv[jn2]);
            }
        }
        bi = (bi == 2) ? 0 : bi + 1;
        bs = (bs == 2) ? 0 : bs + 1;
    }

    // ---- quad-reduce partial l once, then normalize + store ----
#pragma unroll
    for (int i = 0; i < 4; i++) {
        lrun[i] += __shfl_xor_sync(0xFFFFFFFF, lrun[i], 1);
        lrun[i] += __shfl_xor_sync(0xFFFFFFFF, lrun[i], 2);
    }
#pragma unroll
    for (int mi = 0; mi < 2; mi++) {
        const float il0 = 1.f / lrun[2 * mi];
        const float il1 = 1.f / lrun[2 * mi + 1];
        __half* O0 = Out + ((size_t)(b * SEQ + qr0 + 16 * mi + g)) * DIM + h * HD;
        __half* O1 = Out + ((size_t)(b * SEQ + qr0 + 16 * mi + g + 8)) * DIM + h * HD;
#pragma unroll
        for (int jn2 = 0; jn2 < 8; jn2++) {
            *(uint32_t*)&O0[8 * jn2 + 2 * tig] =
                pack_h2(oacc[mi][jn2][0] * il0, oacc[mi][jn2][1] * il0);
            *(uint32_t*)&O1[8 * jn2 + 2 * tig] =
                pack_h2(oacc[mi][jn2][2] * il1, oacc[mi][jn2][3] * il1);
        }
    }
}

// ---------------------------------------------------------------------------
extern "C" void kernel_launch(void* const* d_in, const int* in_sizes, int n_in,
                              void* d_out, int out_size) {
    const float* q  = (const float*)d_in[0];
    const float* k  = (const float*)d_in[1];
    const float* v  = (const float*)d_in[2];
    const int* mask = (const int*)d_in[3];
    const float* Wq = (const float*)d_in[4];
    const float* bq = (const float*)d_in[5];
    const float* Wk = (const float*)d_in[6];
    const float* bk = (const float*)d_in[7];
    const float* Wv = (const float*)d_in[8];
    const float* bv = (const float*)d_in[9];
    const float* Wo = (const float*)d_in[10];
    const float* bo = (const float*)d_in[11];
    float* out = (float*)d_out;

    __half *pQ, *pK, *pV, *pA, *pWh, *pXh;
    float* pBm;
    uint32_t* pMw;
    cudaGetSymbolAddress((void**)&pQ, g_Q);
    cudaGetSymbolAddress((void**)&pK, g_K);
    cudaGetSymbolAddress((void**)&pV, g_V);
    cudaGetSymbolAddress((void**)&pA, g_A);
    cudaGetSymbolAddress((void**)&pWh, g_Wh);
    cudaGetSymbolAddress((void**)&pXh, g_Xh);
    cudaGetSymbolAddress((void**)&pBm, g_bias_m);
    cudaGetSymbolAddress((void**)&pMw, g_mword);

    cudaFuncSetAttribute(gemm_qkv, cudaFuncAttributeMaxDynamicSharedMemorySize, SM_GEMM_TOTAL);
    cudaFuncSetAttribute(gemm_out, cudaFuncAttributeMaxDynamicSharedMemorySize, SM_GEMM_TOTAL);
    cudaFuncSetAttribute(flash_attn_tc, cudaFuncAttributeMaxDynamicSharedMemorySize, FLASH_SMEM_BYTES);

    // --- fused fp32 -> fp16 pre-pass + mask prep ---
    const int W8 = DIM * DIM / 8;       // 131072
    const int X8 = MROWS * DIM / 8;     // 524288
    ConvArgs ca;
    ca.src[0] = Wq; ca.dst[0] = pWh + 0 * (size_t)DIM * DIM; ca.n8[0] = W8;
    ca.src[1] = Wk; ca.dst[1] = pWh + 1 * (size_t)DIM * DIM; ca.n8[1] = W8;
    ca.src[2] = Wv; ca.dst[2] = pWh + 2 * (size_t)DIM * DIM; ca.n8[2] = W8;
    ca.src[3] = Wo; ca.dst[3] = pWh + 3 * (size_t)DIM * DIM; ca.n8[3] = W8;
    ca.src[4] = q;  ca.dst[4] = pXh + 0 * (size_t)MROWS * DIM; ca.n8[4] = X8;
    ca.src[5] = k;  ca.dst[5] = pXh + 1 * (size_t)MROWS * DIM; ca.n8[5] = X8;
    ca.src[6] = v;  ca.dst[6] = pXh + 2 * (size_t)MROWS * DIM; ca.n8[6] = X8;
    ca.mask = mask;
    ca.bias_m = pBm;
    ca.mword = pMw;
    conv_f16_all<<<dim3(X8 / 1024, 8), 256>>>(ca);

    GemmArgs aq{pXh + 0 * (size_t)MROWS * DIM, pWh + 0 * (size_t)DIM * DIM, bq, pQ, CS};
    GemmArgs ak{pXh + 1 * (size_t)MROWS * DIM, pWh + 1 * (size_t)DIM * DIM, bk, pK, 1.0f};
    GemmArgs av{pXh + 2 * (size_t)MROWS * DIM, pWh + 2 * (size_t)DIM * DIM, bv, pV, 1.0f};

    dim3 gqkv(DIM / GBN, MROWS / GBM, 3);   // (8, 32, 3) = 768 CTAs
    gemm_qkv<<<gqkv, 256, SM_GEMM_TOTAL>>>(aq, ak, av);

    flash_attn_tc<<<dim3(SEQ / 128, NH, BATCH), 128, FLASH_SMEM_BYTES>>>(pA);

    dim3 go(DIM / GBN, MROWS / GBM);        // (8, 32) = 256 CTAs
    gemm_out<<<go, 256, SM_GEMM_TOTAL>>>(pA, pWh + 3 * (size_t)DIM * DIM, bo, out);
}